// round 5
// baseline (speedup 1.0000x reference)
#include <cuda_runtime.h>
#include <cuda_bf16.h>
#include <math.h>

#define Bz 16
#define Sz 512
#define Hz 512
#define Vz 10000
#define Gz 2048
#define NCTA 128

// ---- scratch (static device globals) ----
__device__ float g_emb [Bz*Sz*Hz];
__device__ float g_xproj[Bz*Sz*Gz];
__device__ float g_hs0 [Bz*Sz*Hz];
__device__ float g_hs1 [Bz*Sz*Hz];
__device__ float g_hid [Bz*Sz*128];
__device__ __nv_bfloat16 g_hhi[2][Bz*Hz];   // [buf][b*512 + u] split-bf16 h
__device__ __nv_bfloat16 g_hlo[2][Bz*Hz];
__device__ unsigned g_bar[2];

// ------------------------------------------------------------------
__global__ void reset_kernel() { g_bar[0] = 0u; g_bar[1] = 0u; }

__global__ void embed_kernel(const int* __restrict__ src,
                             const float* __restrict__ w_emb,
                             const float* __restrict__ b_emb)
{
    int idx = blockIdx.x * 256 + threadIdx.x;
    if (idx >= Bz*Sz*Hz) return;
    int h  = idx & (Hz-1);
    int bs = idx >> 9;
    int v  = src[bs];
    g_emb[idx] = w_emb[h*Vz + v] + b_emb[h];
}

// ------------------------------------------------------------------
// tf32 tensor-core GEMM (unchanged from R4 — proven).
__device__ __forceinline__ unsigned f2tf(float f) {
    unsigned u;
    asm("cvt.rna.tf32.f32 %0, %1;" : "=r"(u) : "f"(f));
    return u;
}
__device__ __forceinline__ void mma_tf32(float* d, const unsigned* a,
                                         const unsigned* b) {
    asm("mma.sync.aligned.m16n8k8.row.col.f32.tf32.tf32.f32 "
        "{%0,%1,%2,%3}, {%4,%5,%6,%7}, {%8,%9}, {%0,%1,%2,%3};"
        : "+f"(d[0]), "+f"(d[1]), "+f"(d[2]), "+f"(d[3])
        : "r"(a[0]), "r"(a[1]), "r"(a[2]), "r"(a[3]),
          "r"(b[0]), "r"(b[1]));
}

__global__ void __launch_bounds__(256)
gemm_tf32(const float* __restrict__ A, const float* __restrict__ B,
          const float* __restrict__ bias, const float* __restrict__ bias2,
          float* __restrict__ C, int M, int N, int K, int relu)
{
    __shared__ unsigned As[8*4*4*32];
    __shared__ unsigned Bs[16*4*2*32];

    const int tid = threadIdx.x;
    const int n0 = blockIdx.x * 128;
    const int m0 = blockIdx.y * 128;

    const int lm = tid >> 1;
    const int lk = (tid & 1) * 16;
    const float* Ap = A + (size_t)(m0 + lm) * K + lk;
    const float* Bp = B + (size_t)(n0 + lm) * K + lk;
    const bool bval = (n0 + lm) < N;

    const int warp = tid >> 5;
    const int lane = tid & 31;
    const int wm = warp >> 2;
    const int wn = warp & 3;

    float acc[4][4][4];
#pragma unroll
    for (int i = 0; i < 4; i++)
#pragma unroll
        for (int j = 0; j < 4; j++)
#pragma unroll
            for (int r = 0; r < 4; r++) acc[i][j][r] = 0.f;

    float4 a_r[4], b_r[4];
    const float4 z4 = make_float4(0.f, 0.f, 0.f, 0.f);
#pragma unroll
    for (int j = 0; j < 4; j++) {
        a_r[j] = *(const float4*)(Ap + 4*j);
        b_r[j] = bval ? *(const float4*)(Bp + 4*j) : z4;
    }

    const int mt_s = lm >> 4, r_s = lm & 15;
    const int nt_s = lm >> 3, ln_s = lm & 7;
    const int nch = K >> 5;

    for (int ch = 0; ch < nch; ch++) {
        __syncthreads();
#pragma unroll
        for (int j = 0; j < 4; j++) {
            int kc = lk + 4*j;
            int ks = kc >> 3;
            int cr = (kc & 7) >> 2;
            uint4 av = make_uint4(f2tf(a_r[j].x), f2tf(a_r[j].y),
                                  f2tf(a_r[j].z), f2tf(a_r[j].w));
            *(uint4*)&As[(((mt_s*4 + ks)*4) + cr*2 + (r_s >> 3))*32 + (r_s & 7)*4] = av;
            uint4 bv = make_uint4(f2tf(b_r[j].x), f2tf(b_r[j].y),
                                  f2tf(b_r[j].z), f2tf(b_r[j].w));
            *(uint4*)&Bs[(((nt_s*4 + ks)*2) + cr)*32 + ln_s*4] = bv;
        }
        __syncthreads();

        if (ch + 1 < nch) {
            const float* ap = Ap + (ch + 1)*32;
            const float* bp = Bp + (ch + 1)*32;
#pragma unroll
            for (int j = 0; j < 4; j++) {
                a_r[j] = *(const float4*)(ap + 4*j);
                b_r[j] = bval ? *(const float4*)(bp + 4*j) : z4;
            }
        }

#pragma unroll
        for (int ks = 0; ks < 4; ks++) {
            unsigned af[4][4];
#pragma unroll
            for (int mi = 0; mi < 4; mi++) {
                int base = (((wm*4 + mi)*4 + ks)*4)*32 + lane;
                af[mi][0] = As[base];
                af[mi][1] = As[base + 32];
                af[mi][2] = As[base + 64];
                af[mi][3] = As[base + 96];
            }
#pragma unroll
            for (int ni = 0; ni < 4; ni++) {
                int bb = (((wn*4 + ni)*4 + ks)*2)*32 + lane;
                unsigned bf[2] = { Bs[bb], Bs[bb + 32] };
#pragma unroll
                for (int mi = 0; mi < 4; mi++)
                    mma_tf32(acc[mi][ni], af[mi], bf);
            }
        }
    }

    const int g  = lane >> 2;
    const int tg = lane & 3;
#pragma unroll
    for (int ni = 0; ni < 4; ni++) {
        int ncol = n0 + wn*32 + ni*8 + tg*2;
        if (ncol < N) {
            float bb0 = bias[ncol]   + (bias2 ? bias2[ncol]   : 0.f);
            float bb1 = bias[ncol+1] + (bias2 ? bias2[ncol+1] : 0.f);
#pragma unroll
            for (int mi = 0; mi < 4; mi++) {
                int mrow = m0 + wm*64 + mi*16 + g;
                float2 v0 = make_float2(acc[mi][ni][0] + bb0,
                                        acc[mi][ni][1] + bb1);
                float2 v1 = make_float2(acc[mi][ni][2] + bb0,
                                        acc[mi][ni][3] + bb1);
                if (relu) {
                    v0.x = fmaxf(v0.x, 0.f); v0.y = fmaxf(v0.y, 0.f);
                    v1.x = fmaxf(v1.x, 0.f); v1.y = fmaxf(v1.y, 0.f);
                }
                *(float2*)(C + (size_t)mrow * N + ncol)       = v0;
                *(float2*)(C + (size_t)(mrow + 8) * N + ncol) = v1;
            }
        }
    }
}

// ------------------------------------------------------------------
// Tensor-core persistent LSTM scan. 128 CTAs x 256 threads; CTA owns 4
// hidden units (16 gate rows x 16 batch). Split-bf16 MMA (hi/lo), static
// A fragments in registers, B fragments ldcg'd from transposed h arrays,
// xproj software-pipelined, atomic-counter grid barrier.
__device__ __forceinline__ void grid_barrier(unsigned* ctr, unsigned target)
{
    __syncthreads();
    if (threadIdx.x == 0) {
        __threadfence();
        atomicAdd(ctr, 1u);
        while (*((volatile unsigned*)ctr) < target) { }
    }
    __syncthreads();
}

__device__ __forceinline__ unsigned pack_bf2(__nv_bfloat16 a, __nv_bfloat16 b) {
    return ((unsigned)__bfloat16_as_ushort(b) << 16) | __bfloat16_as_ushort(a);
}

__device__ __forceinline__ void mma_bf16(float* d, const unsigned* a,
                                         unsigned b0, unsigned b1) {
    asm("mma.sync.aligned.m16n8k16.row.col.f32.bf16.bf16.f32 "
        "{%0,%1,%2,%3}, {%4,%5,%6,%7}, {%8,%9}, {%0,%1,%2,%3};"
        : "+f"(d[0]), "+f"(d[1]), "+f"(d[2]), "+f"(d[3])
        : "r"(a[0]), "r"(a[1]), "r"(a[2]), "r"(a[3]), "r"(b0), "r"(b1));
}

__global__ void __launch_bounds__(256)
lstm_scan_tc(const float* __restrict__ xproj, const float* __restrict__ w_hh,
             float* __restrict__ hs, unsigned* __restrict__ ctr)
{
    __shared__ float w_s[512*16];      // init staging (32KB)
    __shared__ float part[8*256];      // per-warp partials [w][lg*16+b]
    __shared__ float act_s[256];
    __shared__ float c_s[64];

    const int tid  = threadIdx.x;
    const int u0   = blockIdx.x * 4;
    const int warp = tid >> 5;
    const int lane = tid & 31;
    const int g    = lane >> 2;
    const int tg   = lane & 3;

    // stage w_hh slice: w_s[k][lg], lg = gatetype*4 + unit
    for (int idx = tid; idx < 16*512; idx += 256) {
        int lg = idx >> 9;
        int k  = idx & 511;
        int gate = (lg >> 2) * Hz + u0 + (lg & 3);
        w_s[k*16 + lg] = w_hh[(size_t)gate * Hz + k];
    }
    if (tid < 64) {
        c_s[tid] = 0.f;
        int ul = tid >> 4, b = tid & 15;
        g_hhi[0][b*Hz + u0 + ul] = __float2bfloat16(0.f);
        g_hlo[0][b*Hz + u0 + ul] = __float2bfloat16(0.f);
    }
    __syncthreads();

    // static A fragments (m16n8k16): warp k-range [warp*64, warp*64+64)
    unsigned ahi[4][4], alo[4][4];
#pragma unroll
    for (int ks = 0; ks < 4; ks++) {
        int kb = warp*64 + ks*16 + 2*tg;
#pragma unroll
        for (int r = 0; r < 4; r++) {
            int row = g + (r & 1) * 8;
            int kk  = kb + (r >> 1) * 8;
            float w0 = w_s[kk*16 + row];
            float w1 = w_s[(kk+1)*16 + row];
            __nv_bfloat16 h0 = __float2bfloat16(w0);
            __nv_bfloat16 h1 = __float2bfloat16(w1);
            __nv_bfloat16 l0 = __float2bfloat16(w0 - __bfloat162float(h0));
            __nv_bfloat16 l1 = __float2bfloat16(w1 - __bfloat162float(h1));
            ahi[ks][r] = pack_bf2(h0, h1);
            alo[ks][r] = pack_bf2(l0, l1);
        }
    }

    // xproj mapping for reduce thread (lg, b) = (tid>>4, tid&15)
    const int lg_t = tid >> 4;
    const int b_t  = tid & 15;
    const size_t xp_gate = (size_t)((lg_t >> 2) * Hz + u0 + (lg_t & 3));
    float xp_r = xproj[((size_t)(b_t * Sz)) * Gz + xp_gate];   // t = 0

    unsigned epoch = 1;
    grid_barrier(ctr, NCTA * epoch);

    for (int t = 0; t < Sz; t++) {
        const __nv_bfloat16* Hhi = g_hhi[t & 1];
        const __nv_bfloat16* Hlo = g_hlo[t & 1];

        // B fragments: n = nt*8 + g, k = warp*64 + ks*16 + 2tg (+8 for b1)
        unsigned bh[4][2][2], bl[4][2][2];
#pragma unroll
        for (int ks = 0; ks < 4; ks++) {
            int k = warp*64 + ks*16 + 2*tg;
#pragma unroll
            for (int nt = 0; nt < 2; nt++) {
                int n = nt*8 + g;
                const unsigned* phi = (const unsigned*)(Hhi + n*Hz + k);
                const unsigned* plo = (const unsigned*)(Hlo + n*Hz + k);
                bh[ks][nt][0] = __ldcg(phi);
                bh[ks][nt][1] = __ldcg(phi + 4);
                bl[ks][nt][0] = __ldcg(plo);
                bl[ks][nt][1] = __ldcg(plo + 4);
            }
        }

        // prefetch next xproj (hidden under MMA + barrier)
        int tn = (t + 1 < Sz) ? t + 1 : t;
        float xp_next = xproj[((size_t)(b_t * Sz + tn)) * Gz + xp_gate];

        // 6 accumulation chains: per nt {hihi, hilo, lohi}
        float aA0[4] = {0,0,0,0}, aB0[4] = {0,0,0,0}, aC0[4] = {0,0,0,0};
        float aA1[4] = {0,0,0,0}, aB1[4] = {0,0,0,0}, aC1[4] = {0,0,0,0};
#pragma unroll
        for (int ks = 0; ks < 4; ks++) {
            mma_bf16(aA0, ahi[ks], bh[ks][0][0], bh[ks][0][1]);
            mma_bf16(aA1, ahi[ks], bh[ks][1][0], bh[ks][1][1]);
            mma_bf16(aB0, ahi[ks], bl[ks][0][0], bl[ks][0][1]);
            mma_bf16(aB1, ahi[ks], bl[ks][1][0], bl[ks][1][1]);
            mma_bf16(aC0, alo[ks], bh[ks][0][0], bh[ks][0][1]);
            mma_bf16(aC1, alo[ks], bh[ks][1][0], bh[ks][1][1]);
        }
        float acc0[4], acc1[4];
#pragma unroll
        for (int r = 0; r < 4; r++) {
            acc0[r] = aA0[r] + aB0[r] + aC0[r];
            acc1[r] = aA1[r] + aB1[r] + aC1[r];
        }

        // partials: part[warp][lg*16 + b]; c0,c1 -> (g, 2tg/2tg+1), c2,c3 -> g+8
        float* pw = part + warp*256;
        *(float2*)&pw[g*16 + 2*tg]          = make_float2(acc0[0], acc0[1]);
        *(float2*)&pw[(g+8)*16 + 2*tg]      = make_float2(acc0[2], acc0[3]);
        *(float2*)&pw[g*16 + 8 + 2*tg]      = make_float2(acc1[0], acc1[1]);
        *(float2*)&pw[(g+8)*16 + 8 + 2*tg]  = make_float2(acc1[2], acc1[3]);
        __syncthreads();

        // reduce across warps + activation
        {
            float s = xp_r;
#pragma unroll
            for (int w = 0; w < 8; w++) s += part[w*256 + tid];
            int j = tid >> 6;  // 0=i 1=f 2=g 3=o
            act_s[tid] = (j == 2) ? tanhf(s) : 1.f / (1.f + expf(-s));
        }
        __syncthreads();

        if (tid < 64) {
            int ul = tid >> 4, b = tid & 15;
            float iv = act_s[tid];
            float fv = act_s[tid + 64];
            float gv = act_s[tid + 128];
            float ov = act_s[tid + 192];
            float c = fv * c_s[tid] + iv * gv;
            c_s[tid] = c;
            float h = ov * tanhf(c);
            __nv_bfloat16 hh = __float2bfloat16(h);
            __nv_bfloat16 hl = __float2bfloat16(h - __bfloat162float(hh));
            int buf = (t + 1) & 1;
            g_hhi[buf][b*Hz + u0 + ul] = hh;
            g_hlo[buf][b*Hz + u0 + ul] = hl;
            hs[((size_t)(b * Sz + t)) * Hz + u0 + ul] = h;
        }
        xp_r = xp_next;
        epoch++;
        grid_barrier(ctr, NCTA * epoch);
    }
}

// ------------------------------------------------------------------
extern "C" void kernel_launch(void* const* d_in, const int* in_sizes, int n_in,
                              void* d_out, int out_size)
{
    const int*   src   = (const int*)  d_in[0];
    const float* w_emb = (const float*)d_in[1];
    const float* b_emb = (const float*)d_in[2];
    const float* w_ih0 = (const float*)d_in[3];
    const float* w_hh0 = (const float*)d_in[4];
    const float* b_ih0 = (const float*)d_in[5];
    const float* b_hh0 = (const float*)d_in[6];
    const float* w_ih1 = (const float*)d_in[7];
    const float* w_hh1 = (const float*)d_in[8];
    const float* b_ih1 = (const float*)d_in[9];
    const float* b_hh1 = (const float*)d_in[10];
    const float* w1    = (const float*)d_in[11];
    const float* b1    = (const float*)d_in[12];
    const float* w2    = (const float*)d_in[13];
    const float* b2    = (const float*)d_in[14];
    float* out = (float*)d_out;

    float *emb, *xp, *hs0, *hs1, *hid;
    unsigned* bar;
    cudaGetSymbolAddress((void**)&emb, g_emb);
    cudaGetSymbolAddress((void**)&xp,  g_xproj);
    cudaGetSymbolAddress((void**)&hs0, g_hs0);
    cudaGetSymbolAddress((void**)&hs1, g_hs1);
    cudaGetSymbolAddress((void**)&hid, g_hid);
    cudaGetSymbolAddress((void**)&bar, g_bar);

    const int M = Bz * Sz;  // 8192

    embed_kernel<<<(M*Hz + 255)/256, 256>>>(src, w_emb, b_emb);
    reset_kernel<<<1, 1>>>();

    gemm_tf32<<<dim3(Gz/128, M/128), 256>>>(emb, w_ih0, b_ih0, b_hh0, xp,
                                            M, Gz, Hz, 0);
    lstm_scan_tc<<<NCTA, 256>>>(xp, w_hh0, hs0, bar);

    gemm_tf32<<<dim3(Gz/128, M/128), 256>>>(hs0, w_ih1, b_ih1, b_hh1, xp,
                                            M, Gz, Hz, 0);
    lstm_scan_tc<<<NCTA, 256>>>(xp, w_hh1, hs1, bar + 1);

    gemm_tf32<<<dim3(1, M/128), 256>>>(hs1, w1, b1, nullptr, hid,
                                       M, 128, Hz, 1);

    gemm_tf32<<<dim3((Vz + 127)/128, M/128), 256>>>(hid, w2, b2, nullptr, out,
                                                    M, Vz, 128, 0);
}

// round 6
// speedup vs baseline: 1.2375x; 1.2375x over previous
#include <cuda_runtime.h>
#include <cuda_bf16.h>
#include <math.h>

#define Bz 16
#define Sz 512
#define Hz 512
#define Vz 10000
#define Gz 2048
#define NCTA 128

// ---- scratch (static device globals) ----
__device__ float g_emb [Bz*Sz*Hz];
__device__ float g_xproj[Bz*Sz*Gz];
__device__ float g_hs0 [Bz*Sz*Hz];
__device__ float g_hs1 [Bz*Sz*Hz];
__device__ float g_hid [Bz*Sz*128];
__device__ __nv_bfloat16 g_hhi[2][Bz*Hz];   // [buf][b*512 + u] split-bf16 h
__device__ __nv_bfloat16 g_hlo[2][Bz*Hz];
__device__ unsigned g_bar[4];               // [ctr0, go0, ctr1, go1]

// ------------------------------------------------------------------
__global__ void reset_kernel() {
    if (threadIdx.x < 4) g_bar[threadIdx.x] = 0u;
}

__global__ void embed_kernel(const int* __restrict__ src,
                             const float* __restrict__ w_emb,
                             const float* __restrict__ b_emb)
{
    int idx = blockIdx.x * 256 + threadIdx.x;
    if (idx >= Bz*Sz*Hz) return;
    int h  = idx & (Hz-1);
    int bs = idx >> 9;
    int v  = src[bs];
    g_emb[idx] = w_emb[h*Vz + v] + b_emb[h];
}

// ------------------------------------------------------------------
// tf32 tensor-core GEMM (unchanged from R4 — proven).
__device__ __forceinline__ unsigned f2tf(float f) {
    unsigned u;
    asm("cvt.rna.tf32.f32 %0, %1;" : "=r"(u) : "f"(f));
    return u;
}
__device__ __forceinline__ void mma_tf32(float* d, const unsigned* a,
                                         const unsigned* b) {
    asm("mma.sync.aligned.m16n8k8.row.col.f32.tf32.tf32.f32 "
        "{%0,%1,%2,%3}, {%4,%5,%6,%7}, {%8,%9}, {%0,%1,%2,%3};"
        : "+f"(d[0]), "+f"(d[1]), "+f"(d[2]), "+f"(d[3])
        : "r"(a[0]), "r"(a[1]), "r"(a[2]), "r"(a[3]),
          "r"(b[0]), "r"(b[1]));
}

__global__ void __launch_bounds__(256)
gemm_tf32(const float* __restrict__ A, const float* __restrict__ B,
          const float* __restrict__ bias, const float* __restrict__ bias2,
          float* __restrict__ C, int M, int N, int K, int relu)
{
    __shared__ unsigned As[8*4*4*32];
    __shared__ unsigned Bs[16*4*2*32];

    const int tid = threadIdx.x;
    const int n0 = blockIdx.x * 128;
    const int m0 = blockIdx.y * 128;

    const int lm = tid >> 1;
    const int lk = (tid & 1) * 16;
    const float* Ap = A + (size_t)(m0 + lm) * K + lk;
    const float* Bp = B + (size_t)(n0 + lm) * K + lk;
    const bool bval = (n0 + lm) < N;

    const int warp = tid >> 5;
    const int lane = tid & 31;
    const int wm = warp >> 2;
    const int wn = warp & 3;

    float acc[4][4][4];
#pragma unroll
    for (int i = 0; i < 4; i++)
#pragma unroll
        for (int j = 0; j < 4; j++)
#pragma unroll
            for (int r = 0; r < 4; r++) acc[i][j][r] = 0.f;

    float4 a_r[4], b_r[4];
    const float4 z4 = make_float4(0.f, 0.f, 0.f, 0.f);
#pragma unroll
    for (int j = 0; j < 4; j++) {
        a_r[j] = *(const float4*)(Ap + 4*j);
        b_r[j] = bval ? *(const float4*)(Bp + 4*j) : z4;
    }

    const int mt_s = lm >> 4, r_s = lm & 15;
    const int nt_s = lm >> 3, ln_s = lm & 7;
    const int nch = K >> 5;

    for (int ch = 0; ch < nch; ch++) {
        __syncthreads();
#pragma unroll
        for (int j = 0; j < 4; j++) {
            int kc = lk + 4*j;
            int ks = kc >> 3;
            int cr = (kc & 7) >> 2;
            uint4 av = make_uint4(f2tf(a_r[j].x), f2tf(a_r[j].y),
                                  f2tf(a_r[j].z), f2tf(a_r[j].w));
            *(uint4*)&As[(((mt_s*4 + ks)*4) + cr*2 + (r_s >> 3))*32 + (r_s & 7)*4] = av;
            uint4 bv = make_uint4(f2tf(b_r[j].x), f2tf(b_r[j].y),
                                  f2tf(b_r[j].z), f2tf(b_r[j].w));
            *(uint4*)&Bs[(((nt_s*4 + ks)*2) + cr)*32 + ln_s*4] = bv;
        }
        __syncthreads();

        if (ch + 1 < nch) {
            const float* ap = Ap + (ch + 1)*32;
            const float* bp = Bp + (ch + 1)*32;
#pragma unroll
            for (int j = 0; j < 4; j++) {
                a_r[j] = *(const float4*)(ap + 4*j);
                b_r[j] = bval ? *(const float4*)(bp + 4*j) : z4;
            }
        }

#pragma unroll
        for (int ks = 0; ks < 4; ks++) {
            unsigned af[4][4];
#pragma unroll
            for (int mi = 0; mi < 4; mi++) {
                int base = (((wm*4 + mi)*4 + ks)*4)*32 + lane;
                af[mi][0] = As[base];
                af[mi][1] = As[base + 32];
                af[mi][2] = As[base + 64];
                af[mi][3] = As[base + 96];
            }
#pragma unroll
            for (int ni = 0; ni < 4; ni++) {
                int bb = (((wn*4 + ni)*4 + ks)*2)*32 + lane;
                unsigned bf[2] = { Bs[bb], Bs[bb + 32] };
#pragma unroll
                for (int mi = 0; mi < 4; mi++)
                    mma_tf32(acc[mi][ni], af[mi], bf);
            }
        }
    }

    const int g  = lane >> 2;
    const int tg = lane & 3;
#pragma unroll
    for (int ni = 0; ni < 4; ni++) {
        int ncol = n0 + wn*32 + ni*8 + tg*2;
        if (ncol < N) {
            float bb0 = bias[ncol]   + (bias2 ? bias2[ncol]   : 0.f);
            float bb1 = bias[ncol+1] + (bias2 ? bias2[ncol+1] : 0.f);
#pragma unroll
            for (int mi = 0; mi < 4; mi++) {
                int mrow = m0 + wm*64 + mi*16 + g;
                float2 v0 = make_float2(acc[mi][ni][0] + bb0,
                                        acc[mi][ni][1] + bb1);
                float2 v1 = make_float2(acc[mi][ni][2] + bb0,
                                        acc[mi][ni][3] + bb1);
                if (relu) {
                    v0.x = fmaxf(v0.x, 0.f); v0.y = fmaxf(v0.y, 0.f);
                    v1.x = fmaxf(v1.x, 0.f); v1.y = fmaxf(v1.y, 0.f);
                }
                *(float2*)(C + (size_t)mrow * N + ncol)       = v0;
                *(float2*)(C + (size_t)(mrow + 8) * N + ncol) = v1;
            }
        }
    }
}

// ------------------------------------------------------------------
// Leader/go-flag grid barrier: red (no return) arrivals, one poller.
__device__ __forceinline__ void grid_barrier2(unsigned* ctr, unsigned* go,
                                              unsigned epoch)
{
    __syncthreads();
    if (threadIdx.x == 0) {
        asm volatile("red.release.gpu.global.add.u32 [%0], 1;"
                     :: "l"(ctr) : "memory");
        if (blockIdx.x == 0) {
            unsigned v;
            do {
                asm volatile("ld.acquire.gpu.global.u32 %0, [%1];"
                             : "=r"(v) : "l"(ctr) : "memory");
            } while (v < NCTA * epoch);
            asm volatile("st.release.gpu.global.u32 [%0], %1;"
                         :: "l"(go), "r"(epoch) : "memory");
        }
        unsigned gv;
        do {
            asm volatile("ld.acquire.gpu.global.u32 %0, [%1];"
                         : "=r"(gv) : "l"(go) : "memory");
        } while (gv < epoch);
    }
    __syncthreads();
}

__device__ __forceinline__ unsigned pack_bf2(__nv_bfloat16 a, __nv_bfloat16 b) {
    return ((unsigned)__bfloat16_as_ushort(b) << 16) | __bfloat16_as_ushort(a);
}

__device__ __forceinline__ void mma_bf16(float* d, const unsigned* a,
                                         unsigned b0, unsigned b1) {
    asm("mma.sync.aligned.m16n8k16.row.col.f32.bf16.bf16.f32 "
        "{%0,%1,%2,%3}, {%4,%5,%6,%7}, {%8,%9}, {%0,%1,%2,%3};"
        : "+f"(d[0]), "+f"(d[1]), "+f"(d[2]), "+f"(d[3])
        : "r"(a[0]), "r"(a[1]), "r"(a[2]), "r"(a[3]), "r"(b0), "r"(b1));
}

// HS: padded SMEM row stride for h tiles (conflict-free fragment reads)
#define HPAD 520

__global__ void __launch_bounds__(256)
lstm_scan_tc(const float* __restrict__ xproj, const float* __restrict__ w_hh,
             float* __restrict__ hs, unsigned* __restrict__ bar)
{
    // union: w staging (32KB, init only) / h hi+lo tiles (33.3KB, loop)
    __shared__ __align__(16) unsigned char smu[2*16*HPAD*2];
    float* w_s = (float*)smu;                               // [512][16]
    __nv_bfloat16* Hhi_s = (__nv_bfloat16*)smu;             // [16][520]
    __nv_bfloat16* Hlo_s = (__nv_bfloat16*)smu + 16*HPAD;   // [16][520]
    __shared__ float part[8*256];
    __shared__ float act_s[256];
    __shared__ float c_s[64];

    const int tid  = threadIdx.x;
    const int u0   = blockIdx.x * 4;
    const int warp = tid >> 5;
    const int lane = tid & 31;
    const int g    = lane >> 2;
    const int tg   = lane & 3;

    unsigned* ctr = bar;
    unsigned* go  = bar + 1;

    // stage w_hh slice: w_s[k][lg], lg = gatetype*4 + unit
    for (int idx = tid; idx < 16*512; idx += 256) {
        int lg = idx >> 9;
        int k  = idx & 511;
        int gate = (lg >> 2) * Hz + u0 + (lg & 3);
        w_s[k*16 + lg] = w_hh[(size_t)gate * Hz + k];
    }
    if (tid < 64) {
        c_s[tid] = 0.f;
        int ul = tid >> 4, b = tid & 15;
        g_hhi[0][b*Hz + u0 + ul] = __float2bfloat16(0.f);
        g_hlo[0][b*Hz + u0 + ul] = __float2bfloat16(0.f);
    }
    __syncthreads();

    // static A fragments (m16n8k16): warp k-range [warp*64, warp*64+64)
    unsigned ahi[4][4], alo[4][4];
#pragma unroll
    for (int ks = 0; ks < 4; ks++) {
        int kb = warp*64 + ks*16 + 2*tg;
#pragma unroll
        for (int r = 0; r < 4; r++) {
            int row = g + (r & 1) * 8;
            int kk  = kb + (r >> 1) * 8;
            float w0 = w_s[kk*16 + row];
            float w1 = w_s[(kk+1)*16 + row];
            __nv_bfloat16 h0 = __float2bfloat16(w0);
            __nv_bfloat16 h1 = __float2bfloat16(w1);
            __nv_bfloat16 l0 = __float2bfloat16(w0 - __bfloat162float(h0));
            __nv_bfloat16 l1 = __float2bfloat16(w1 - __bfloat162float(h1));
            ahi[ks][r] = pack_bf2(h0, h1);
            alo[ks][r] = pack_bf2(l0, l1);
        }
    }

    // xproj mapping for reduce thread (lg, b) = (tid>>4, tid&15)
    const int lg_t = tid >> 4;
    const int b_t  = tid & 15;
    const size_t xp_gate = (size_t)((lg_t >> 2) * Hz + u0 + (lg_t & 3));
    float xp_r = xproj[((size_t)(b_t * Sz)) * Gz + xp_gate];   // t = 0

    unsigned epoch = 1;
    grid_barrier2(ctr, go, epoch);    // also orders A-frag reads vs H writes

    for (int t = 0; t < Sz; t++) {
        // coalesced load of full h (hi+lo) into padded SMEM tiles
        {
            const uint4* ghi = (const uint4*)g_hhi[t & 1];
            const uint4* glo = (const uint4*)g_hlo[t & 1];
#pragma unroll
            for (int i = 0; i < 4; i++) {
                int idx = tid + 256*i;           // uint4 index (8 bf16)
                int b   = idx >> 6;
                int uo  = (idx & 63) * 8;
                uint4 vh = __ldcg(ghi + idx);
                uint4 vl = __ldcg(glo + idx);
                *(uint4*)(Hhi_s + b*HPAD + uo) = vh;
                *(uint4*)(Hlo_s + b*HPAD + uo) = vl;
            }
        }
        // prefetch next xproj (hidden under staging + MMA)
        int tn = (t + 1 < Sz) ? t + 1 : t;
        float xp_next = xproj[((size_t)(b_t * Sz + tn)) * Gz + xp_gate];
        __syncthreads();

        // B fragments from SMEM (conflict-free), then 6 MMA chains
        float aA0[4] = {0,0,0,0}, aB0[4] = {0,0,0,0}, aC0[4] = {0,0,0,0};
        float aA1[4] = {0,0,0,0}, aB1[4] = {0,0,0,0}, aC1[4] = {0,0,0,0};
#pragma unroll
        for (int ks = 0; ks < 4; ks++) {
            int k = warp*64 + ks*16 + 2*tg;
            unsigned bh0[2], bh1[2], bl0[2], bl1[2];
            {
                const __nv_bfloat16* p0 = Hhi_s + g*HPAD + k;        // n = g
                const __nv_bfloat16* p1 = Hhi_s + (8 + g)*HPAD + k;  // n = 8+g
                bh0[0] = *(const unsigned*)p0;
                bh0[1] = *(const unsigned*)(p0 + 8);
                bh1[0] = *(const unsigned*)p1;
                bh1[1] = *(const unsigned*)(p1 + 8);
                const __nv_bfloat16* q0 = Hlo_s + g*HPAD + k;
                const __nv_bfloat16* q1 = Hlo_s + (8 + g)*HPAD + k;
                bl0[0] = *(const unsigned*)q0;
                bl0[1] = *(const unsigned*)(q0 + 8);
                bl1[0] = *(const unsigned*)q1;
                bl1[1] = *(const unsigned*)(q1 + 8);
            }
            mma_bf16(aA0, ahi[ks], bh0[0], bh0[1]);
            mma_bf16(aA1, ahi[ks], bh1[0], bh1[1]);
            mma_bf16(aB0, ahi[ks], bl0[0], bl0[1]);
            mma_bf16(aB1, ahi[ks], bl1[0], bl1[1]);
            mma_bf16(aC0, alo[ks], bh0[0], bh0[1]);
            mma_bf16(aC1, alo[ks], bh1[0], bh1[1]);
        }
        float acc0[4], acc1[4];
#pragma unroll
        for (int r = 0; r < 4; r++) {
            acc0[r] = aA0[r] + aB0[r] + aC0[r];
            acc1[r] = aA1[r] + aB1[r] + aC1[r];
        }
        __syncthreads();   // done reading H tiles (reused next iter)

        // partials: part[warp][lg*16 + b]
        float* pw = part + warp*256;
        *(float2*)&pw[g*16 + 2*tg]          = make_float2(acc0[0], acc0[1]);
        *(float2*)&pw[(g+8)*16 + 2*tg]      = make_float2(acc0[2], acc0[3]);
        *(float2*)&pw[g*16 + 8 + 2*tg]      = make_float2(acc1[0], acc1[1]);
        *(float2*)&pw[(g+8)*16 + 8 + 2*tg]  = make_float2(acc1[2], acc1[3]);
        __syncthreads();

        // reduce across warps + activation
        {
            float s = xp_r;
#pragma unroll
            for (int w = 0; w < 8; w++) s += part[w*256 + tid];
            int j = tid >> 6;  // 0=i 1=f 2=g 3=o
            act_s[tid] = (j == 2) ? tanhf(s) : 1.f / (1.f + expf(-s));
        }
        __syncthreads();

        if (tid < 64) {
            int ul = tid >> 4, b = tid & 15;
            float iv = act_s[tid];
            float fv = act_s[tid + 64];
            float gv = act_s[tid + 128];
            float ov = act_s[tid + 192];
            float c = fv * c_s[tid] + iv * gv;
            c_s[tid] = c;
            float h = ov * tanhf(c);
            __nv_bfloat16 hh = __float2bfloat16(h);
            __nv_bfloat16 hl = __float2bfloat16(h - __bfloat162float(hh));
            int buf = (t + 1) & 1;
            g_hhi[buf][b*Hz + u0 + ul] = hh;
            g_hlo[buf][b*Hz + u0 + ul] = hl;
            hs[((size_t)(b * Sz + t)) * Hz + u0 + ul] = h;
        }
        xp_r = xp_next;
        epoch++;
        grid_barrier2(ctr, go, epoch);
    }
}

// ------------------------------------------------------------------
extern "C" void kernel_launch(void* const* d_in, const int* in_sizes, int n_in,
                              void* d_out, int out_size)
{
    const int*   src   = (const int*)  d_in[0];
    const float* w_emb = (const float*)d_in[1];
    const float* b_emb = (const float*)d_in[2];
    const float* w_ih0 = (const float*)d_in[3];
    const float* w_hh0 = (const float*)d_in[4];
    const float* b_ih0 = (const float*)d_in[5];
    const float* b_hh0 = (const float*)d_in[6];
    const float* w_ih1 = (const float*)d_in[7];
    const float* w_hh1 = (const float*)d_in[8];
    const float* b_ih1 = (const float*)d_in[9];
    const float* b_hh1 = (const float*)d_in[10];
    const float* w1    = (const float*)d_in[11];
    const float* b1    = (const float*)d_in[12];
    const float* w2    = (const float*)d_in[13];
    const float* b2    = (const float*)d_in[14];
    float* out = (float*)d_out;

    float *emb, *xp, *hs0, *hs1, *hid;
    unsigned* bar;
    cudaGetSymbolAddress((void**)&emb, g_emb);
    cudaGetSymbolAddress((void**)&xp,  g_xproj);
    cudaGetSymbolAddress((void**)&hs0, g_hs0);
    cudaGetSymbolAddress((void**)&hs1, g_hs1);
    cudaGetSymbolAddress((void**)&hid, g_hid);
    cudaGetSymbolAddress((void**)&bar, g_bar);

    const int M = Bz * Sz;  // 8192

    embed_kernel<<<(M*Hz + 255)/256, 256>>>(src, w_emb, b_emb);
    reset_kernel<<<1, 32>>>();

    gemm_tf32<<<dim3(Gz/128, M/128), 256>>>(emb, w_ih0, b_ih0, b_hh0, xp,
                                            M, Gz, Hz, 0);
    lstm_scan_tc<<<NCTA, 256>>>(xp, w_hh0, hs0, bar);

    gemm_tf32<<<dim3(Gz/128, M/128), 256>>>(hs0, w_ih1, b_ih1, b_hh1, xp,
                                            M, Gz, Hz, 0);
    lstm_scan_tc<<<NCTA, 256>>>(xp, w_hh1, hs1, bar + 2);

    gemm_tf32<<<dim3(1, M/128), 256>>>(hs1, w1, b1, nullptr, hid,
                                       M, 128, Hz, 1);

    gemm_tf32<<<dim3((Vz + 127)/128, M/128), 256>>>(hid, w2, b2, nullptr, out,
                                                    M, Vz, 128, 0);
}

// round 7
// speedup vs baseline: 1.7263x; 1.3951x over previous
#include <cuda_runtime.h>
#include <cuda_bf16.h>
#include <math.h>

#define Bz 16
#define Sz 512
#define Hz 512
#define Vz 10000
#define Gz 2048
#define NCTA 96
#define HP 1032

// ---- scratch (static device globals) ----
__device__ float g_emb [Bz*Sz*Hz];
__device__ float g_xproj[Bz*Sz*Gz];
__device__ float g_hs1 [Bz*Sz*Hz];
__device__ float g_hid [Bz*Sz*128];
__device__ __align__(16) __nv_bfloat16 g_h0hi[2][Bz*Hz];
__device__ __align__(16) __nv_bfloat16 g_h0lo[2][Bz*Hz];
__device__ __align__(16) __nv_bfloat16 g_h1hi[2][Bz*Hz];
__device__ __align__(16) __nv_bfloat16 g_h1lo[2][Bz*Hz];
__device__ unsigned g_bar[4];

// ------------------------------------------------------------------
__global__ void reset_kernel() {
    if (threadIdx.x < 4) g_bar[threadIdx.x] = 0u;
}

__global__ void embed_kernel(const int* __restrict__ src,
                             const float* __restrict__ w_emb,
                             const float* __restrict__ b_emb)
{
    int idx = blockIdx.x * 256 + threadIdx.x;
    if (idx >= Bz*Sz*Hz) return;
    int h  = idx & (Hz-1);
    int bs = idx >> 9;
    int v  = src[bs];
    g_emb[idx] = w_emb[h*Vz + v] + b_emb[h];
}

// ------------------------------------------------------------------
// tf32 tensor-core GEMM (unchanged — proven R4).
__device__ __forceinline__ unsigned f2tf(float f) {
    unsigned u;
    asm("cvt.rna.tf32.f32 %0, %1;" : "=r"(u) : "f"(f));
    return u;
}
__device__ __forceinline__ void mma_tf32(float* d, const unsigned* a,
                                         const unsigned* b) {
    asm("mma.sync.aligned.m16n8k8.row.col.f32.tf32.tf32.f32 "
        "{%0,%1,%2,%3}, {%4,%5,%6,%7}, {%8,%9}, {%0,%1,%2,%3};"
        : "+f"(d[0]), "+f"(d[1]), "+f"(d[2]), "+f"(d[3])
        : "r"(a[0]), "r"(a[1]), "r"(a[2]), "r"(a[3]),
          "r"(b[0]), "r"(b[1]));
}

__global__ void __launch_bounds__(256)
gemm_tf32(const float* __restrict__ A, const float* __restrict__ B,
          const float* __restrict__ bias, const float* __restrict__ bias2,
          float* __restrict__ C, int M, int N, int K, int relu)
{
    __shared__ unsigned As[8*4*4*32];
    __shared__ unsigned Bs[16*4*2*32];

    const int tid = threadIdx.x;
    const int n0 = blockIdx.x * 128;
    const int m0 = blockIdx.y * 128;

    const int lm = tid >> 1;
    const int lk = (tid & 1) * 16;
    const float* Ap = A + (size_t)(m0 + lm) * K + lk;
    const float* Bp = B + (size_t)(n0 + lm) * K + lk;
    const bool bval = (n0 + lm) < N;

    const int warp = tid >> 5;
    const int lane = tid & 31;
    const int wm = warp >> 2;
    const int wn = warp & 3;

    float acc[4][4][4];
#pragma unroll
    for (int i = 0; i < 4; i++)
#pragma unroll
        for (int j = 0; j < 4; j++)
#pragma unroll
            for (int r = 0; r < 4; r++) acc[i][j][r] = 0.f;

    float4 a_r[4], b_r[4];
    const float4 z4 = make_float4(0.f, 0.f, 0.f, 0.f);
#pragma unroll
    for (int j = 0; j < 4; j++) {
        a_r[j] = *(const float4*)(Ap + 4*j);
        b_r[j] = bval ? *(const float4*)(Bp + 4*j) : z4;
    }

    const int mt_s = lm >> 4, r_s = lm & 15;
    const int nt_s = lm >> 3, ln_s = lm & 7;
    const int nch = K >> 5;

    for (int ch = 0; ch < nch; ch++) {
        __syncthreads();
#pragma unroll
        for (int j = 0; j < 4; j++) {
            int kc = lk + 4*j;
            int ks = kc >> 3;
            int cr = (kc & 7) >> 2;
            uint4 av = make_uint4(f2tf(a_r[j].x), f2tf(a_r[j].y),
                                  f2tf(a_r[j].z), f2tf(a_r[j].w));
            *(uint4*)&As[(((mt_s*4 + ks)*4) + cr*2 + (r_s >> 3))*32 + (r_s & 7)*4] = av;
            uint4 bv = make_uint4(f2tf(b_r[j].x), f2tf(b_r[j].y),
                                  f2tf(b_r[j].z), f2tf(b_r[j].w));
            *(uint4*)&Bs[(((nt_s*4 + ks)*2) + cr)*32 + ln_s*4] = bv;
        }
        __syncthreads();

        if (ch + 1 < nch) {
            const float* ap = Ap + (ch + 1)*32;
            const float* bp = Bp + (ch + 1)*32;
#pragma unroll
            for (int j = 0; j < 4; j++) {
                a_r[j] = *(const float4*)(ap + 4*j);
                b_r[j] = bval ? *(const float4*)(bp + 4*j) : z4;
            }
        }

#pragma unroll
        for (int ks = 0; ks < 4; ks++) {
            unsigned af[4][4];
#pragma unroll
            for (int mi = 0; mi < 4; mi++) {
                int base = (((wm*4 + mi)*4 + ks)*4)*32 + lane;
                af[mi][0] = As[base];
                af[mi][1] = As[base + 32];
                af[mi][2] = As[base + 64];
                af[mi][3] = As[base + 96];
            }
#pragma unroll
            for (int ni = 0; ni < 4; ni++) {
                int bb = (((wn*4 + ni)*4 + ks)*2)*32 + lane;
                unsigned bf[2] = { Bs[bb], Bs[bb + 32] };
#pragma unroll
                for (int mi = 0; mi < 4; mi++)
                    mma_tf32(acc[mi][ni], af[mi], bf);
            }
        }
    }

    const int g  = lane >> 2;
    const int tg = lane & 3;
#pragma unroll
    for (int ni = 0; ni < 4; ni++) {
        int ncol = n0 + wn*32 + ni*8 + tg*2;
        if (ncol < N) {
            float bb0 = bias[ncol]   + (bias2 ? bias2[ncol]   : 0.f);
            float bb1 = bias[ncol+1] + (bias2 ? bias2[ncol+1] : 0.f);
#pragma unroll
            for (int mi = 0; mi < 4; mi++) {
                int mrow = m0 + wm*64 + mi*16 + g;
                float2 v0 = make_float2(acc[mi][ni][0] + bb0,
                                        acc[mi][ni][1] + bb1);
                float2 v1 = make_float2(acc[mi][ni][2] + bb0,
                                        acc[mi][ni][3] + bb1);
                if (relu) {
                    v0.x = fmaxf(v0.x, 0.f); v0.y = fmaxf(v0.y, 0.f);
                    v1.x = fmaxf(v1.x, 0.f); v1.y = fmaxf(v1.y, 0.f);
                }
                *(float2*)(C + (size_t)mrow * N + ncol)       = v0;
                *(float2*)(C + (size_t)(mrow + 8) * N + ncol) = v1;
            }
        }
    }
}

// ------------------------------------------------------------------
__device__ __forceinline__ void grid_barrier2(unsigned* ctr, unsigned* go,
                                              unsigned epoch)
{
    __syncthreads();
    if (threadIdx.x == 0) {
        asm volatile("red.release.gpu.global.add.u32 [%0], 1;"
                     :: "l"(ctr) : "memory");
        if (blockIdx.x == 0) {
            unsigned v;
            do {
                asm volatile("ld.acquire.gpu.global.u32 %0, [%1];"
                             : "=r"(v) : "l"(ctr) : "memory");
            } while (v < NCTA * epoch);
            asm volatile("st.release.gpu.global.u32 [%0], %1;"
                         :: "l"(go), "r"(epoch) : "memory");
        }
        unsigned gv;
        do {
            asm volatile("ld.acquire.gpu.global.u32 %0, [%1];"
                         : "=r"(gv) : "l"(go) : "memory");
        } while (gv < epoch);
    }
    __syncthreads();
}

__device__ __forceinline__ unsigned pack_bf2(__nv_bfloat16 a, __nv_bfloat16 b) {
    return ((unsigned)__bfloat16_as_ushort(b) << 16) | __bfloat16_as_ushort(a);
}

__device__ __forceinline__ void mma_bf16(float* d, const unsigned* a,
                                         unsigned b0, unsigned b1) {
    asm("mma.sync.aligned.m16n8k16.row.col.f32.bf16.bf16.f32 "
        "{%0,%1,%2,%3}, {%4,%5,%6,%7}, {%8,%9}, {%0,%1,%2,%3};"
        : "+f"(d[0]), "+f"(d[1]), "+f"(d[2]), "+f"(d[3])
        : "r"(a[0]), "r"(a[1]), "r"(a[2]), "r"(a[3]), "r"(b0), "r"(b1));
}

// ------------------------------------------------------------------
// Fused 2-layer LSTM scan. 96 CTAs: bid<32 -> layer0 (16 units each),
// bid>=32 -> layer1 (8 units, k=1024 concat [w_ih1|w_hh1]@[h0_t;h1_{t-1}]).
// Wavefront: round r: L0 computes h0_r, L1 computes h1_{r-1}. 513 rounds.
__global__ void __launch_bounds__(256)
lstm_fused(const float* __restrict__ xproj,
           const float* __restrict__ w_hh0,
           const float* __restrict__ w_ih1,
           const float* __restrict__ w_hh1,
           const float* __restrict__ b_ih1,
           const float* __restrict__ b_hh1,
           float* __restrict__ hs1,
           unsigned* __restrict__ bar)
{
    extern __shared__ __align__(16) unsigned char dyn[];
    unsigned* a_hi = (unsigned*)dyn;                       // [128 fg][32][4]
    unsigned* a_lo = a_hi + 16384;
    __nv_bfloat16* Hhi_s = (__nv_bfloat16*)(a_lo + 16384); // [16][HP]
    __nv_bfloat16* Hlo_s = Hhi_s + 16*HP;
    float* part  = (float*)(Hlo_s + 16*HP);                // [2048]
    float* act_s = part + 2048;                            // [1024]
    float* c_s   = act_s + 1024;                           // [256]

    const int tid  = threadIdx.x;
    const int bid  = blockIdx.x;
    const bool is0 = bid < 32;
    const int u0   = is0 ? bid*16 : (bid-32)*8;
    const int warp = tid >> 5;
    const int lane = tid & 31;
    const int g    = lane >> 2;
    const int tg   = lane & 3;
    unsigned* ctr = bar;
    unsigned* go  = bar + 1;

    // ---- stage A fragments (split-bf16, fragment order) ----
    for (int idx = tid; idx < 128*32; idx += 256) {
        int fg = idx >> 5, ln = idx & 31;
        int gg = ln >> 2, tt = ln & 3;
        int mt, ks;
        if (is0) { mt = fg >> 5; ks = fg & 31; }
        else     { mt = fg >> 6; ks = fg & 63; }
        unsigned hi4[4], lo4[4];
#pragma unroll
        for (int r = 0; r < 4; r++) {
            int row = mt*16 + gg + (r & 1)*8;
            int k   = ks*16 + 2*tt + (r >> 1)*8;
            const float* W;
            int gate, koff;
            if (is0) {
                gate = (row >> 4)*Hz + u0 + (row & 15);
                W = w_hh0; koff = k;
            } else {
                gate = (row >> 3)*Hz + u0 + (row & 7);
                if (k < Hz) { W = w_ih1; koff = k; }
                else        { W = w_hh1; koff = k - Hz; }
            }
            float w0 = W[(size_t)gate*Hz + koff];
            float w1 = W[(size_t)gate*Hz + koff + 1];
            __nv_bfloat16 h0 = __float2bfloat16(w0);
            __nv_bfloat16 h1 = __float2bfloat16(w1);
            __nv_bfloat16 l0 = __float2bfloat16(w0 - __bfloat162float(h0));
            __nv_bfloat16 l1 = __float2bfloat16(w1 - __bfloat162float(h1));
            hi4[r] = pack_bf2(h0, h1);
            lo4[r] = pack_bf2(l0, l1);
        }
        *(uint4*)&a_hi[idx*4] = make_uint4(hi4[0], hi4[1], hi4[2], hi4[3]);
        *(uint4*)&a_lo[idx*4] = make_uint4(lo4[0], lo4[1], lo4[2], lo4[3]);
    }

    float base_r[4];
    const __nv_bfloat16 zb = __float2bfloat16(0.f);
    if (is0) {
        c_s[tid] = 0.f;
        int u = u0 + (tid >> 4), b = tid & 15;
        g_h0hi[1][b*Hz + u] = zb;
        g_h0lo[1][b*Hz + u] = zb;
#pragma unroll
        for (int j = 0; j < 4; j++) {
            int idx = tid + 256*j;
            int lg = idx >> 4, b2 = idx & 15;
            int gate = (lg >> 4)*Hz + u0 + (lg & 15);
            base_r[j] = xproj[((size_t)(b2 << 9))*Gz + gate];   // t = 0
        }
    } else {
        if (tid < 128) {
            c_s[tid] = 0.f;
            int u = u0 + (tid >> 4), b = tid & 15;
            g_h1hi[1][b*Hz + u] = zb;
            g_h1lo[1][b*Hz + u] = zb;
        }
#pragma unroll
        for (int j = 0; j < 2; j++) {
            int idx = tid + 256*j;
            int lg = idx >> 4;
            int gate = (lg >> 3)*Hz + u0 + (lg & 7);
            base_r[j] = b_ih1[gate] + b_hh1[gate];
        }
    }

    unsigned epoch = 1;
    grid_barrier2(ctr, go, epoch);

    for (int r = 0; r <= Sz; r++) {
        if (is0) {
            if (r < Sz) {
                const int t = r;
                // load h0_{t-1} (buf (t-1)&1) into SMEM tiles
                const uint4* ghi = (const uint4*)g_h0hi[(t & 1) ^ 1];
                const uint4* glo = (const uint4*)g_h0lo[(t & 1) ^ 1];
#pragma unroll
                for (int i = 0; i < 4; i++) {
                    int idx = tid + 256*i;
                    int b = idx >> 6, uo = (idx & 63)*8;
                    uint4 vh = __ldcg(ghi + idx);
                    uint4 vl = __ldcg(glo + idx);
                    *(uint4*)(Hhi_s + b*HP + uo) = vh;
                    *(uint4*)(Hlo_s + b*HP + uo) = vl;
                }
                // prefetch next xproj
                float nxt[4];
                int tn = (t + 1 < Sz) ? t + 1 : t;
#pragma unroll
                for (int j = 0; j < 4; j++) {
                    int idx = tid + 256*j;
                    int lg = idx >> 4, b2 = idx & 15;
                    int gate = (lg >> 4)*Hz + u0 + (lg & 15);
                    nxt[j] = xproj[((size_t)((b2 << 9) | tn))*Gz + gate];
                }
                __syncthreads();

                const int mt = warp & 3, kg = warp >> 2;
                float aA0[4]={0,0,0,0}, aB0[4]={0,0,0,0}, aC0[4]={0,0,0,0};
                float aA1[4]={0,0,0,0}, aB1[4]={0,0,0,0}, aC1[4]={0,0,0,0};
#pragma unroll
                for (int kk = 0; kk < 16; kk++) {
                    int ks = kg*16 + kk;
                    int fg = mt*32 + ks;
                    uint4 ah = *(const uint4*)&a_hi[fg*128 + lane*4];
                    uint4 al = *(const uint4*)&a_lo[fg*128 + lane*4];
                    unsigned afh[4] = {ah.x, ah.y, ah.z, ah.w};
                    unsigned afl[4] = {al.x, al.y, al.z, al.w};
                    int k0 = ks*16 + 2*tg;
                    const __nv_bfloat16* p0 = Hhi_s + g*HP + k0;
                    const __nv_bfloat16* p1 = Hhi_s + (8+g)*HP + k0;
                    const __nv_bfloat16* q0 = Hlo_s + g*HP + k0;
                    const __nv_bfloat16* q1 = Hlo_s + (8+g)*HP + k0;
                    unsigned bh00 = *(const unsigned*)p0;
                    unsigned bh01 = *(const unsigned*)(p0 + 8);
                    unsigned bh10 = *(const unsigned*)p1;
                    unsigned bh11 = *(const unsigned*)(p1 + 8);
                    unsigned bl00 = *(const unsigned*)q0;
                    unsigned bl01 = *(const unsigned*)(q0 + 8);
                    unsigned bl10 = *(const unsigned*)q1;
                    unsigned bl11 = *(const unsigned*)(q1 + 8);
                    mma_bf16(aA0, afh, bh00, bh01);
                    mma_bf16(aA1, afh, bh10, bh11);
                    mma_bf16(aB0, afh, bl00, bl01);
                    mma_bf16(aB1, afh, bl10, bl11);
                    mma_bf16(aC0, afl, bh00, bh01);
                    mma_bf16(aC1, afl, bh10, bh11);
                }
                float acc0[4], acc1[4];
#pragma unroll
                for (int q = 0; q < 4; q++) {
                    acc0[q] = aA0[q] + aB0[q] + aC0[q];
                    acc1[q] = aA1[q] + aB1[q] + aC1[q];
                }
                float* pw = part + kg*1024;
                *(float2*)&pw[(mt*16 + g)*16 + 2*tg]         = make_float2(acc0[0], acc0[1]);
                *(float2*)&pw[(mt*16 + g + 8)*16 + 2*tg]     = make_float2(acc0[2], acc0[3]);
                *(float2*)&pw[(mt*16 + g)*16 + 8 + 2*tg]     = make_float2(acc1[0], acc1[1]);
                *(float2*)&pw[(mt*16 + g + 8)*16 + 8 + 2*tg] = make_float2(acc1[2], acc1[3]);
                __syncthreads();

#pragma unroll
                for (int j = 0; j < 4; j++) {
                    int idx = tid + 256*j;
                    float s = base_r[j] + part[idx] + part[1024 + idx];
                    int gt = idx >> 8;
                    act_s[idx] = (gt == 2) ? tanhf(s) : 1.f/(1.f + expf(-s));
                }
                __syncthreads();

                {
                    float iv = act_s[tid];
                    float fv = act_s[256 + tid];
                    float gv = act_s[512 + tid];
                    float ov = act_s[768 + tid];
                    float c = fv*c_s[tid] + iv*gv;
                    c_s[tid] = c;
                    float h = ov*tanhf(c);
                    __nv_bfloat16 hh = __float2bfloat16(h);
                    __nv_bfloat16 hl = __float2bfloat16(h - __bfloat162float(hh));
                    int u = u0 + (tid >> 4), b = tid & 15;
                    g_h0hi[t & 1][b*Hz + u] = hh;
                    g_h0lo[t & 1][b*Hz + u] = hl;
                }
#pragma unroll
                for (int j = 0; j < 4; j++) base_r[j] = nxt[j];
            }
        } else {
            if (r >= 1) {
                const int t = r - 1;
                // h0_t (buf t&1) -> cols [0,512); h1_{t-1} (buf (t&1)^1) -> [512,1024)
                const uint4* g0h = (const uint4*)g_h0hi[t & 1];
                const uint4* g0l = (const uint4*)g_h0lo[t & 1];
                const uint4* g1h = (const uint4*)g_h1hi[(t & 1) ^ 1];
                const uint4* g1l = (const uint4*)g_h1lo[(t & 1) ^ 1];
#pragma unroll
                for (int i = 0; i < 4; i++) {
                    int idx = tid + 256*i;
                    int b = idx >> 6, uo = (idx & 63)*8;
                    uint4 vh = __ldcg(g0h + idx);
                    uint4 vl = __ldcg(g0l + idx);
                    *(uint4*)(Hhi_s + b*HP + uo) = vh;
                    *(uint4*)(Hlo_s + b*HP + uo) = vl;
                    uint4 wh = __ldcg(g1h + idx);
                    uint4 wl = __ldcg(g1l + idx);
                    *(uint4*)(Hhi_s + b*HP + 512 + uo) = wh;
                    *(uint4*)(Hlo_s + b*HP + 512 + uo) = wl;
                }
                __syncthreads();

                const int mt = warp & 1, kg = warp >> 1;
                float aA0[4]={0,0,0,0}, aB0[4]={0,0,0,0}, aC0[4]={0,0,0,0};
                float aA1[4]={0,0,0,0}, aB1[4]={0,0,0,0}, aC1[4]={0,0,0,0};
#pragma unroll
                for (int kk = 0; kk < 16; kk++) {
                    int ks = kg*16 + kk;
                    int fg = mt*64 + ks;
                    uint4 ah = *(const uint4*)&a_hi[fg*128 + lane*4];
                    uint4 al = *(const uint4*)&a_lo[fg*128 + lane*4];
                    unsigned afh[4] = {ah.x, ah.y, ah.z, ah.w};
                    unsigned afl[4] = {al.x, al.y, al.z, al.w};
                    int k0 = ks*16 + 2*tg;
                    const __nv_bfloat16* p0 = Hhi_s + g*HP + k0;
                    const __nv_bfloat16* p1 = Hhi_s + (8+g)*HP + k0;
                    const __nv_bfloat16* q0 = Hlo_s + g*HP + k0;
                    const __nv_bfloat16* q1 = Hlo_s + (8+g)*HP + k0;
                    unsigned bh00 = *(const unsigned*)p0;
                    unsigned bh01 = *(const unsigned*)(p0 + 8);
                    unsigned bh10 = *(const unsigned*)p1;
                    unsigned bh11 = *(const unsigned*)(p1 + 8);
                    unsigned bl00 = *(const unsigned*)q0;
                    unsigned bl01 = *(const unsigned*)(q0 + 8);
                    unsigned bl10 = *(const unsigned*)q1;
                    unsigned bl11 = *(const unsigned*)(q1 + 8);
                    mma_bf16(aA0, afh, bh00, bh01);
                    mma_bf16(aA1, afh, bh10, bh11);
                    mma_bf16(aB0, afh, bl00, bl01);
                    mma_bf16(aB1, afh, bl10, bl11);
                    mma_bf16(aC0, afl, bh00, bh01);
                    mma_bf16(aC1, afl, bh10, bh11);
                }
                float acc0[4], acc1[4];
#pragma unroll
                for (int q = 0; q < 4; q++) {
                    acc0[q] = aA0[q] + aB0[q] + aC0[q];
                    acc1[q] = aA1[q] + aB1[q] + aC1[q];
                }
                float* pw = part + kg*512;
                *(float2*)&pw[(mt*16 + g)*16 + 2*tg]         = make_float2(acc0[0], acc0[1]);
                *(float2*)&pw[(mt*16 + g + 8)*16 + 2*tg]     = make_float2(acc0[2], acc0[3]);
                *(float2*)&pw[(mt*16 + g)*16 + 8 + 2*tg]     = make_float2(acc1[0], acc1[1]);
                *(float2*)&pw[(mt*16 + g + 8)*16 + 8 + 2*tg] = make_float2(acc1[2], acc1[3]);
                __syncthreads();

#pragma unroll
                for (int j = 0; j < 2; j++) {
                    int idx = tid + 256*j;
                    if (idx < 512) {
                        float s = base_r[j] + part[idx] + part[512 + idx]
                                + part[1024 + idx] + part[1536 + idx];
                        int gt = idx >> 7;
                        act_s[idx] = (gt == 2) ? tanhf(s) : 1.f/(1.f + expf(-s));
                    }
                }
                __syncthreads();

                if (tid < 128) {
                    float iv = act_s[tid];
                    float fv = act_s[128 + tid];
                    float gv = act_s[256 + tid];
                    float ov = act_s[384 + tid];
                    float c = fv*c_s[tid] + iv*gv;
                    c_s[tid] = c;
                    float h = ov*tanhf(c);
                    __nv_bfloat16 hh = __float2bfloat16(h);
                    __nv_bfloat16 hl = __float2bfloat16(h - __bfloat162float(hh));
                    int u = u0 + (tid >> 4), b = tid & 15;
                    g_h1hi[t & 1][b*Hz + u] = hh;
                    g_h1lo[t & 1][b*Hz + u] = hl;
                    hs1[((size_t)(b*Sz + t))*Hz + u] = h;
                }
            }
        }
        epoch++;
        grid_barrier2(ctr, go, epoch);
    }
}

// ------------------------------------------------------------------
extern "C" void kernel_launch(void* const* d_in, const int* in_sizes, int n_in,
                              void* d_out, int out_size)
{
    const int*   src   = (const int*)  d_in[0];
    const float* w_emb = (const float*)d_in[1];
    const float* b_emb = (const float*)d_in[2];
    const float* w_ih0 = (const float*)d_in[3];
    const float* w_hh0 = (const float*)d_in[4];
    const float* b_ih0 = (const float*)d_in[5];
    const float* b_hh0 = (const float*)d_in[6];
    const float* w_ih1 = (const float*)d_in[7];
    const float* w_hh1 = (const float*)d_in[8];
    const float* b_ih1 = (const float*)d_in[9];
    const float* b_hh1 = (const float*)d_in[10];
    const float* w1    = (const float*)d_in[11];
    const float* b1    = (const float*)d_in[12];
    const float* w2    = (const float*)d_in[13];
    const float* b2    = (const float*)d_in[14];
    float* out = (float*)d_out;

    float *emb, *xp, *hs1, *hid;
    unsigned* bar;
    cudaGetSymbolAddress((void**)&emb, g_emb);
    cudaGetSymbolAddress((void**)&xp,  g_xproj);
    cudaGetSymbolAddress((void**)&hs1, g_hs1);
    cudaGetSymbolAddress((void**)&hid, g_hid);
    cudaGetSymbolAddress((void**)&bar, g_bar);

    const int DSMEM = (16384 + 16384)*4 + 2*16*HP*2 + (2048 + 1024 + 256)*4;
    cudaFuncSetAttribute(lstm_fused, cudaFuncAttributeMaxDynamicSharedMemorySize,
                         DSMEM);

    const int M = Bz * Sz;  // 8192

    embed_kernel<<<(M*Hz + 255)/256, 256>>>(src, w_emb, b_emb);
    reset_kernel<<<1, 32>>>();

    // layer-0 x-projection (includes b_ih0 + b_hh0)
    gemm_tf32<<<dim3(Gz/128, M/128), 256>>>(emb, w_ih0, b_ih0, b_hh0, xp,
                                            M, Gz, Hz, 0);

    // fused 2-layer scan (layer-1 xproj folded in)
    lstm_fused<<<NCTA, 256, DSMEM>>>(xp, w_hh0, w_ih1, w_hh1, b_ih1, b_hh1,
                                     hs1, bar);

    gemm_tf32<<<dim3(1, M/128), 256>>>(hs1, w1, b1, nullptr, hid,
                                       M, 128, Hz, 1);

    gemm_tf32<<<dim3((Vz + 127)/128, M/128), 256>>>(hid, w2, b2, nullptr, out,
                                                    M, Vz, 128, 0);
}

// round 8
// speedup vs baseline: 2.2343x; 1.2942x over previous
#include <cuda_runtime.h>
#include <cuda_bf16.h>
#include <math.h>

#define Bz 16
#define Sz 512
#define Hz 512
#define Vz 10000
#define Gz 2048
#define HP 1032

// ---- scratch (static device globals) ----
__device__ float g_emb [Bz*Sz*Hz];
__device__ float g_xproj[Bz*Sz*Gz];
__device__ float g_hs1 [Bz*Sz*Hz];
__device__ float g_hid [Bz*Sz*128];
__device__ __align__(16) __nv_bfloat16 g_h0hi[4][Bz*Hz];
__device__ __align__(16) __nv_bfloat16 g_h0lo[4][Bz*Hz];
__device__ __align__(16) __nv_bfloat16 g_h1hi[4][Bz*Hz];
__device__ __align__(16) __nv_bfloat16 g_h1lo[4][Bz*Hz];
__device__ unsigned g_sync[64];   // ctr0 @0, ctr1 @32 (separate lines)

// ------------------------------------------------------------------
__global__ void reset_kernel() {
    if (threadIdx.x < 64) g_sync[threadIdx.x] = 0u;
}

__global__ void embed_kernel(const int* __restrict__ src,
                             const float* __restrict__ w_emb,
                             const float* __restrict__ b_emb)
{
    int idx = blockIdx.x * 256 + threadIdx.x;
    if (idx >= Bz*Sz*Hz) return;
    int h  = idx & (Hz-1);
    int bs = idx >> 9;
    int v  = src[bs];
    g_emb[idx] = w_emb[h*Vz + v] + b_emb[h];
}

// ------------------------------------------------------------------
// tf32 tensor-core GEMM (proven R4, unchanged).
__device__ __forceinline__ unsigned f2tf(float f) {
    unsigned u;
    asm("cvt.rna.tf32.f32 %0, %1;" : "=r"(u) : "f"(f));
    return u;
}
__device__ __forceinline__ void mma_tf32(float* d, const unsigned* a,
                                         const unsigned* b) {
    asm("mma.sync.aligned.m16n8k8.row.col.f32.tf32.tf32.f32 "
        "{%0,%1,%2,%3}, {%4,%5,%6,%7}, {%8,%9}, {%0,%1,%2,%3};"
        : "+f"(d[0]), "+f"(d[1]), "+f"(d[2]), "+f"(d[3])
        : "r"(a[0]), "r"(a[1]), "r"(a[2]), "r"(a[3]),
          "r"(b[0]), "r"(b[1]));
}

__global__ void __launch_bounds__(256)
gemm_tf32(const float* __restrict__ A, const float* __restrict__ B,
          const float* __restrict__ bias, const float* __restrict__ bias2,
          float* __restrict__ C, int M, int N, int K, int relu)
{
    __shared__ unsigned As[8*4*4*32];
    __shared__ unsigned Bs[16*4*2*32];

    const int tid = threadIdx.x;
    const int n0 = blockIdx.x * 128;
    const int m0 = blockIdx.y * 128;

    const int lm = tid >> 1;
    const int lk = (tid & 1) * 16;
    const float* Ap = A + (size_t)(m0 + lm) * K + lk;
    const float* Bp = B + (size_t)(n0 + lm) * K + lk;
    const bool bval = (n0 + lm) < N;

    const int warp = tid >> 5;
    const int lane = tid & 31;
    const int wm = warp >> 2;
    const int wn = warp & 3;

    float acc[4][4][4];
#pragma unroll
    for (int i = 0; i < 4; i++)
#pragma unroll
        for (int j = 0; j < 4; j++)
#pragma unroll
            for (int r = 0; r < 4; r++) acc[i][j][r] = 0.f;

    float4 a_r[4], b_r[4];
    const float4 z4 = make_float4(0.f, 0.f, 0.f, 0.f);
#pragma unroll
    for (int j = 0; j < 4; j++) {
        a_r[j] = *(const float4*)(Ap + 4*j);
        b_r[j] = bval ? *(const float4*)(Bp + 4*j) : z4;
    }

    const int mt_s = lm >> 4, r_s = lm & 15;
    const int nt_s = lm >> 3, ln_s = lm & 7;
    const int nch = K >> 5;

    for (int ch = 0; ch < nch; ch++) {
        __syncthreads();
#pragma unroll
        for (int j = 0; j < 4; j++) {
            int kc = lk + 4*j;
            int ks = kc >> 3;
            int cr = (kc & 7) >> 2;
            uint4 av = make_uint4(f2tf(a_r[j].x), f2tf(a_r[j].y),
                                  f2tf(a_r[j].z), f2tf(a_r[j].w));
            *(uint4*)&As[(((mt_s*4 + ks)*4) + cr*2 + (r_s >> 3))*32 + (r_s & 7)*4] = av;
            uint4 bv = make_uint4(f2tf(b_r[j].x), f2tf(b_r[j].y),
                                  f2tf(b_r[j].z), f2tf(b_r[j].w));
            *(uint4*)&Bs[(((nt_s*4 + ks)*2) + cr)*32 + ln_s*4] = bv;
        }
        __syncthreads();

        if (ch + 1 < nch) {
            const float* ap = Ap + (ch + 1)*32;
            const float* bp = Bp + (ch + 1)*32;
#pragma unroll
            for (int j = 0; j < 4; j++) {
                a_r[j] = *(const float4*)(ap + 4*j);
                b_r[j] = bval ? *(const float4*)(bp + 4*j) : z4;
            }
        }

#pragma unroll
        for (int ks = 0; ks < 4; ks++) {
            unsigned af[4][4];
#pragma unroll
            for (int mi = 0; mi < 4; mi++) {
                int base = (((wm*4 + mi)*4 + ks)*4)*32 + lane;
                af[mi][0] = As[base];
                af[mi][1] = As[base + 32];
                af[mi][2] = As[base + 64];
                af[mi][3] = As[base + 96];
            }
#pragma unroll
            for (int ni = 0; ni < 4; ni++) {
                int bb = (((wn*4 + ni)*4 + ks)*2)*32 + lane;
                unsigned bf[2] = { Bs[bb], Bs[bb + 32] };
#pragma unroll
                for (int mi = 0; mi < 4; mi++)
                    mma_tf32(acc[mi][ni], af[mi], bf);
            }
        }
    }

    const int g  = lane >> 2;
    const int tg = lane & 3;
#pragma unroll
    for (int ni = 0; ni < 4; ni++) {
        int ncol = n0 + wn*32 + ni*8 + tg*2;
        if (ncol < N) {
            float bb0 = bias[ncol]   + (bias2 ? bias2[ncol]   : 0.f);
            float bb1 = bias[ncol+1] + (bias2 ? bias2[ncol+1] : 0.f);
#pragma unroll
            for (int mi = 0; mi < 4; mi++) {
                int mrow = m0 + wm*64 + mi*16 + g;
                float2 v0 = make_float2(acc[mi][ni][0] + bb0,
                                        acc[mi][ni][1] + bb1);
                float2 v1 = make_float2(acc[mi][ni][2] + bb0,
                                        acc[mi][ni][3] + bb1);
                if (relu) {
                    v0.x = fmaxf(v0.x, 0.f); v0.y = fmaxf(v0.y, 0.f);
                    v1.x = fmaxf(v1.x, 0.f); v1.y = fmaxf(v1.y, 0.f);
                }
                *(float2*)(C + (size_t)mrow * N + ncol)       = v0;
                *(float2*)(C + (size_t)(mrow + 8) * N + ncol) = v1;
            }
        }
    }
}

// ------------------------------------------------------------------
__device__ __forceinline__ void poll_ge(unsigned* p, unsigned tgt) {
    unsigned v;
    do {
        asm volatile("ld.acquire.gpu.global.u32 %0, [%1];"
                     : "=r"(v) : "l"(p) : "memory");
    } while (v < tgt);
}
__device__ __forceinline__ void arrive(unsigned* p) {
    asm volatile("red.release.gpu.global.add.u32 [%0], 1;"
                 :: "l"(p) : "memory");
}

__device__ __forceinline__ unsigned pack_bf2(__nv_bfloat16 a, __nv_bfloat16 b) {
    return ((unsigned)__bfloat16_as_ushort(b) << 16) | __bfloat16_as_ushort(a);
}
__device__ __forceinline__ void mma_bf16(float* d, const unsigned* a,
                                         unsigned b0, unsigned b1) {
    asm("mma.sync.aligned.m16n8k16.row.col.f32.bf16.bf16.f32 "
        "{%0,%1,%2,%3}, {%4,%5,%6,%7}, {%8,%9}, {%0,%1,%2,%3};"
        : "+f"(d[0]), "+f"(d[1]), "+f"(d[2]), "+f"(d[3])
        : "r"(a[0]), "r"(a[1]), "r"(a[2]), "r"(a[3]), "r"(b0), "r"(b1));
}
__device__ __forceinline__ void ldsm_x4(unsigned& r0, unsigned& r1,
                                        unsigned& r2, unsigned& r3,
                                        unsigned addr) {
    asm volatile("ldmatrix.sync.aligned.m8n8.x4.shared.b16 {%0,%1,%2,%3}, [%4];"
                 : "=r"(r0), "=r"(r1), "=r"(r2), "=r"(r3) : "r"(addr));
}
__device__ __forceinline__ unsigned smem_u32(const void* p) {
    return (unsigned)__cvta_generic_to_shared(p);
}

// ------------------------------------------------------------------
// Fused 2-layer wavefront LSTM. 96 CTAs: 32 L0 (16 units), 64 L1 (8 units,
// k=1024 concat). Decoupled counters, 4-deep h buffers, reg-resident A
// fragments, ldmatrix B fragments.
__global__ void __launch_bounds__(256)
lstm_fused(const float* __restrict__ xproj,
           const float* __restrict__ w_hh0,
           const float* __restrict__ w_ih1,
           const float* __restrict__ w_hh1,
           const float* __restrict__ b_ih1,
           const float* __restrict__ b_hh1,
           float* __restrict__ hs1)
{
    extern __shared__ __align__(16) unsigned char dyn[];
    float* w_stage = (float*)dyn;                          // 128KB (init only)
    __nv_bfloat16* Hhi_s = (__nv_bfloat16*)(dyn + 131072); // [16][HP]
    __nv_bfloat16* Hlo_s = Hhi_s + 16*HP;
    float* part  = (float*)(Hlo_s + 16*HP);                // [2048]
    float* act_s = part + 2048;                            // [1024]
    float* c_s   = act_s + 1024;                           // [256]

    const int tid  = threadIdx.x;
    const int bid  = blockIdx.x;
    const bool is0 = bid < 32;
    const int u0   = is0 ? bid*16 : (bid-32)*8;
    const int warp = tid >> 5;
    const int lane = tid & 31;
    const int g    = lane >> 2;
    const int tg   = lane & 3;
    unsigned* ctr0 = g_sync;
    unsigned* ctr1 = g_sync + 32;

    const int Kw = is0 ? 512 : 1024;

    // ---- stage weights coalesced into SMEM ----
    for (int idx4 = tid; idx4 < 8192; idx4 += 256) {
        int row, k;
        if (is0) { row = idx4 >> 7; k = (idx4 & 127) * 4; }
        else     { row = idx4 >> 8; k = (idx4 & 255) * 4; }
        const float* W;
        int gate, koff;
        if (is0) {
            gate = (row >> 4)*Hz + u0 + (row & 15);
            W = w_hh0; koff = k;
        } else {
            gate = (row >> 3)*Hz + u0 + (row & 7);
            if (k < Hz) { W = w_ih1; koff = k; }
            else        { W = w_hh1; koff = k - Hz; }
        }
        *(float4*)(w_stage + row*Kw + k) =
            *(const float4*)(W + (size_t)gate*Hz + koff);
    }
    __syncthreads();

    // ---- A fragments -> registers (split-bf16) ----
    const int mt = is0 ? (warp & 3) : (warp & 1);
    const int kg = is0 ? (warp >> 2) : (warp >> 1);
    unsigned Ahi[16][4], Alo[16][4];
#pragma unroll
    for (int kk = 0; kk < 16; kk++) {
        int ks = kg*16 + kk;
#pragma unroll
        for (int r = 0; r < 4; r++) {
            int row = mt*16 + g + (r & 1)*8;
            int k   = ks*16 + 2*tg + (r >> 1)*8;
            float w0 = w_stage[row*Kw + k];
            float w1 = w_stage[row*Kw + k + 1];
            __nv_bfloat16 h0 = __float2bfloat16(w0);
            __nv_bfloat16 h1 = __float2bfloat16(w1);
            __nv_bfloat16 l0 = __float2bfloat16(w0 - __bfloat162float(h0));
            __nv_bfloat16 l1 = __float2bfloat16(w1 - __bfloat162float(h1));
            Ahi[kk][r] = pack_bf2(h0, h1);
            Alo[kk][r] = pack_bf2(l0, l1);
        }
    }

    // ---- ldmatrix lane addressing (B frags) ----
    const int mrow = lane >> 3, rr = lane & 7;
    const int nn   = ((mrow >> 1) << 3) + rr;       // 0..15 (batch)
    const int kof  = (mrow & 1) * 8;
    const unsigned bhi_base = smem_u32(Hhi_s) + (nn*HP + kof)*2;
    const unsigned blo_base = bhi_base + 16*HP*2;

    // ---- init state + base (xproj / bias) ----
    float base_r[4];
    const __nv_bfloat16 zb = __float2bfloat16(0.f);
    if (is0) {
        c_s[tid] = 0.f;
        int u = u0 + (tid >> 4), b = tid & 15;
        g_h0hi[3][b*Hz + u] = zb;                   // h0_{-1} in slot 3
        g_h0lo[3][b*Hz + u] = zb;
#pragma unroll
        for (int j = 0; j < 4; j++) {
            int idx = tid + 256*j;
            int lg = idx >> 4, b2 = idx & 15;
            int gate = (lg >> 4)*Hz + u0 + (lg & 15);
            base_r[j] = xproj[((size_t)(b2 << 9))*Gz + gate];   // t = 0
        }
    } else {
        if (tid < 128) {
            c_s[tid] = 0.f;
            int u = u0 + (tid >> 4), b = tid & 15;
            g_h1hi[3][b*Hz + u] = zb;               // h1_{-1} in slot 3
            g_h1lo[3][b*Hz + u] = zb;
        }
#pragma unroll
        for (int j = 0; j < 2; j++) {
            int idx = tid + 256*j;
            int lg = idx >> 4;
            int gate = (lg >> 3)*Hz + u0 + (lg & 7);
            base_r[j] = b_ih1[gate] + b_hh1[gate];
        }
    }
    __syncthreads();
    if (tid == 0) arrive(is0 ? ctr0 : ctr1);        // init epoch

    if (is0) {
        // ============ LAYER 0: rounds r = 0..511 compute h0_r ============
        for (int r = 0; r < Sz; r++) {
            if (tid < 2) {
                unsigned* p  = (tid == 0) ? ctr0 : ctr1;
                unsigned tgt = (tid == 0) ? 32u*(r+1)
                             : (r >= 3 ? 64u*(r-2) : 0u);
                if (tgt) poll_ge(p, tgt);
            }
            __syncthreads();

            // stage h0_{r-1} (slot (r+3)&3)
            {
                const uint4* ghi = (const uint4*)g_h0hi[(r+3)&3];
                const uint4* glo = (const uint4*)g_h0lo[(r+3)&3];
#pragma unroll
                for (int i = 0; i < 4; i++) {
                    int idx = tid + 256*i;
                    int b = idx >> 6, uo = (idx & 63)*8;
                    uint4 vh = __ldcg(ghi + idx);
                    uint4 vl = __ldcg(glo + idx);
                    *(uint4*)(Hhi_s + b*HP + uo) = vh;
                    *(uint4*)(Hlo_s + b*HP + uo) = vl;
                }
            }
            float nxt[4];
            {
                int tn = (r + 1 < Sz) ? r + 1 : r;
#pragma unroll
                for (int j = 0; j < 4; j++) {
                    int idx = tid + 256*j;
                    int lg = idx >> 4, b2 = idx & 15;
                    int gate = (lg >> 4)*Hz + u0 + (lg & 15);
                    nxt[j] = xproj[((size_t)((b2 << 9) | tn))*Gz + gate];
                }
            }
            __syncthreads();

            float aA0[4]={0,0,0,0}, aB0[4]={0,0,0,0}, aC0[4]={0,0,0,0};
            float aA1[4]={0,0,0,0}, aB1[4]={0,0,0,0}, aC1[4]={0,0,0,0};
#pragma unroll
            for (int kk = 0; kk < 16; kk++) {
                int ks = kg*16 + kk;
                unsigned bh0,bh1,bh2,bh3, bl0,bl1,bl2,bl3;
                ldsm_x4(bh0,bh1,bh2,bh3, bhi_base + ks*32);
                ldsm_x4(bl0,bl1,bl2,bl3, blo_base + ks*32);
                mma_bf16(aA0, Ahi[kk], bh0, bh1);
                mma_bf16(aA1, Ahi[kk], bh2, bh3);
                mma_bf16(aB0, Ahi[kk], bl0, bl1);
                mma_bf16(aB1, Ahi[kk], bl2, bl3);
                mma_bf16(aC0, Alo[kk], bh0, bh1);
                mma_bf16(aC1, Alo[kk], bh2, bh3);
            }
            float acc0[4], acc1[4];
#pragma unroll
            for (int q = 0; q < 4; q++) {
                acc0[q] = aA0[q] + aB0[q] + aC0[q];
                acc1[q] = aA1[q] + aB1[q] + aC1[q];
            }
            float* pw = part + kg*1024;
            *(float2*)&pw[(mt*16 + g)*16 + 2*tg]         = make_float2(acc0[0], acc0[1]);
            *(float2*)&pw[(mt*16 + g + 8)*16 + 2*tg]     = make_float2(acc0[2], acc0[3]);
            *(float2*)&pw[(mt*16 + g)*16 + 8 + 2*tg]     = make_float2(acc1[0], acc1[1]);
            *(float2*)&pw[(mt*16 + g + 8)*16 + 8 + 2*tg] = make_float2(acc1[2], acc1[3]);
            __syncthreads();

#pragma unroll
            for (int j = 0; j < 4; j++) {
                int idx = tid + 256*j;
                float s = base_r[j] + part[idx] + part[1024 + idx];
                int gt = idx >> 8;
                act_s[idx] = (gt == 2) ? tanhf(s) : 1.f/(1.f + expf(-s));
            }
            __syncthreads();

            {
                float iv = act_s[tid];
                float fv = act_s[256 + tid];
                float gv = act_s[512 + tid];
                float ov = act_s[768 + tid];
                float c = fv*c_s[tid] + iv*gv;
                c_s[tid] = c;
                float h = ov*tanhf(c);
                __nv_bfloat16 hh = __float2bfloat16(h);
                __nv_bfloat16 hl = __float2bfloat16(h - __bfloat162float(hh));
                int u = u0 + (tid >> 4), b = tid & 15;
                g_h0hi[r & 3][b*Hz + u] = hh;
                g_h0lo[r & 3][b*Hz + u] = hl;
            }
#pragma unroll
            for (int j = 0; j < 4; j++) base_r[j] = nxt[j];
            __syncthreads();
            if (tid == 0) arrive(ctr0);
        }
    } else {
        // ============ LAYER 1: rounds r = 1..512 compute h1_{r-1} ============
        for (int r = 1; r <= Sz; r++) {
            const int t = r - 1;
            if (tid < 2) {
                unsigned* p  = (tid == 0) ? ctr0 : ctr1;
                unsigned tgt = (tid == 0) ? 32u*(r+1) : 64u*r;
                poll_ge(p, tgt);
            }
            __syncthreads();

            // stage h0_t (slot t&3) -> cols [0,512); h1_{t-1} (slot (t+3)&3) -> [512,1024)
            {
                const uint4* g0h = (const uint4*)g_h0hi[t & 3];
                const uint4* g0l = (const uint4*)g_h0lo[t & 3];
                const uint4* g1h = (const uint4*)g_h1hi[(t+3) & 3];
                const uint4* g1l = (const uint4*)g_h1lo[(t+3) & 3];
#pragma unroll
                for (int i = 0; i < 4; i++) {
                    int idx = tid + 256*i;
                    int b = idx >> 6, uo = (idx & 63)*8;
                    uint4 vh = __ldcg(g0h + idx);
                    uint4 vl = __ldcg(g0l + idx);
                    *(uint4*)(Hhi_s + b*HP + uo) = vh;
                    *(uint4*)(Hlo_s + b*HP + uo) = vl;
                    uint4 wh = __ldcg(g1h + idx);
                    uint4 wl = __ldcg(g1l + idx);
                    *(uint4*)(Hhi_s + b*HP + 512 + uo) = wh;
                    *(uint4*)(Hlo_s + b*HP + 512 + uo) = wl;
                }
            }
            __syncthreads();

            float aA0[4]={0,0,0,0}, aB0[4]={0,0,0,0}, aC0[4]={0,0,0,0};
            float aA1[4]={0,0,0,0}, aB1[4]={0,0,0,0}, aC1[4]={0,0,0,0};
#pragma unroll
            for (int kk = 0; kk < 16; kk++) {
                int ks = kg*16 + kk;
                unsigned bh0,bh1,bh2,bh3, bl0,bl1,bl2,bl3;
                ldsm_x4(bh0,bh1,bh2,bh3, bhi_base + ks*32);
                ldsm_x4(bl0,bl1,bl2,bl3, blo_base + ks*32);
                mma_bf16(aA0, Ahi[kk], bh0, bh1);
                mma_bf16(aA1, Ahi[kk], bh2, bh3);
                mma_bf16(aB0, Ahi[kk], bl0, bl1);
                mma_bf16(aB1, Ahi[kk], bl2, bl3);
                mma_bf16(aC0, Alo[kk], bh0, bh1);
                mma_bf16(aC1, Alo[kk], bh2, bh3);
            }
            float acc0[4], acc1[4];
#pragma unroll
            for (int q = 0; q < 4; q++) {
                acc0[q] = aA0[q] + aB0[q] + aC0[q];
                acc1[q] = aA1[q] + aB1[q] + aC1[q];
            }
            float* pw = part + kg*512;
            *(float2*)&pw[(mt*16 + g)*16 + 2*tg]         = make_float2(acc0[0], acc0[1]);
            *(float2*)&pw[(mt*16 + g + 8)*16 + 2*tg]     = make_float2(acc0[2], acc0[3]);
            *(float2*)&pw[(mt*16 + g)*16 + 8 + 2*tg]     = make_float2(acc1[0], acc1[1]);
            *(float2*)&pw[(mt*16 + g + 8)*16 + 8 + 2*tg] = make_float2(acc1[2], acc1[3]);
            __syncthreads();

#pragma unroll
            for (int j = 0; j < 2; j++) {
                int idx = tid + 256*j;
                if (idx < 512) {
                    float s = base_r[j] + part[idx] + part[512 + idx]
                            + part[1024 + idx] + part[1536 + idx];
                    int gt = idx >> 7;
                    act_s[idx] = (gt == 2) ? tanhf(s) : 1.f/(1.f + expf(-s));
                }
            }
            __syncthreads();

            if (tid < 128) {
                float iv = act_s[tid];
                float fv = act_s[128 + tid];
                float gv = act_s[256 + tid];
                float ov = act_s[384 + tid];
                float c = fv*c_s[tid] + iv*gv;
                c_s[tid] = c;
                float h = ov*tanhf(c);
                __nv_bfloat16 hh = __float2bfloat16(h);
                __nv_bfloat16 hl = __float2bfloat16(h - __bfloat162float(hh));
                int u = u0 + (tid >> 4), b = tid & 15;
                g_h1hi[t & 3][b*Hz + u] = hh;
                g_h1lo[t & 3][b*Hz + u] = hl;
                hs1[((size_t)(b*Sz + t))*Hz + u] = h;
            }
            __syncthreads();
            if (tid == 0) arrive(ctr1);
        }
    }
}

// ------------------------------------------------------------------
extern "C" void kernel_launch(void* const* d_in, const int* in_sizes, int n_in,
                              void* d_out, int out_size)
{
    const int*   src   = (const int*)  d_in[0];
    const float* w_emb = (const float*)d_in[1];
    const float* b_emb = (const float*)d_in[2];
    const float* w_ih0 = (const float*)d_in[3];
    const float* w_hh0 = (const float*)d_in[4];
    const float* b_ih0 = (const float*)d_in[5];
    const float* b_hh0 = (const float*)d_in[6];
    const float* w_ih1 = (const float*)d_in[7];
    const float* w_hh1 = (const float*)d_in[8];
    const float* b_ih1 = (const float*)d_in[9];
    const float* b_hh1 = (const float*)d_in[10];
    const float* w1    = (const float*)d_in[11];
    const float* b1    = (const float*)d_in[12];
    const float* w2    = (const float*)d_in[13];
    const float* b2    = (const float*)d_in[14];
    float* out = (float*)d_out;

    float *emb, *xp, *hs1, *hid;
    cudaGetSymbolAddress((void**)&emb, g_emb);
    cudaGetSymbolAddress((void**)&xp,  g_xproj);
    cudaGetSymbolAddress((void**)&hs1, g_hs1);
    cudaGetSymbolAddress((void**)&hid, g_hid);

    const int DSMEM = 131072 + 2*16*HP*2 + (2048 + 1024 + 256)*4;
    cudaFuncSetAttribute(lstm_fused, cudaFuncAttributeMaxDynamicSharedMemorySize,
                         DSMEM);

    const int M = Bz * Sz;  // 8192

    embed_kernel<<<(M*Hz + 255)/256, 256>>>(src, w_emb, b_emb);
    reset_kernel<<<1, 64>>>();

    gemm_tf32<<<dim3(Gz/128, M/128), 256>>>(emb, w_ih0, b_ih0, b_hh0, xp,
                                            M, Gz, Hz, 0);

    lstm_fused<<<96, 256, DSMEM>>>(xp, w_hh0, w_ih1, w_hh1, b_ih1, b_hh1, hs1);

    gemm_tf32<<<dim3(1, M/128), 256>>>(hs1, w1, b1, nullptr, hid,
                                       M, 128, Hz, 1);

    gemm_tf32<<<dim3((Vz + 127)/128, M/128), 256>>>(hid, w2, b2, nullptr, out,
                                                    M, Vz, 128, 0);
}